// round 13
// baseline (speedup 1.0000x reference)
#include <cuda_runtime.h>
#include <cuda_bf16.h>
#include <cstdint>

#define EPS_LDM 1e-6f

static const int NSEL  = 16384;
static const int DIM   = 128;
static const int NEDGE = 500000;
static const int NTRI2 = 16512;            // 128x64 upper-tri tiles: sum_i (256-2i), i<128
static const int NTC   = 296;              // persistent CTAs = 148 SMs x 2 (one wave)
static const int NW_L  = NTC * 4;          // producer warps doing link work

// Stage = one 64-K-col phase of a 128x64 tile.
static const int ROWB2   = 144;            // 64 bf16 + 8 pad = 144 B rows (ldmatrix conflict-free)
static const int A_BYTES = 128 * ROWB2;    // 18432
static const int B_BYTES = 64 * ROWB2;     //  9216
static const int STAGEB  = A_BYTES + B_BYTES;   // 27648
static const int ACC_STRIDE = 272;         // fp32 acc row stride bytes (68 floats)
static const int ACC_BYTES  = 128 * ACC_STRIDE; // 34816
static const int DSMEM   = 2 * STAGEB + ACC_BYTES + 128;

// Scratch (device globals; no allocation allowed)
__device__ double g_acc[2];                    // [0]=link, [1]=nonlink
__device__ unsigned g_done;
__device__ __nv_bfloat16 g_psb[NSEL * DIM];    // bf16 p_star[nodes_p_star] (rows n)
__device__ __nv_bfloat16 g_ppb[NSEL * DIM];    // bf16 p[nodes_p]           (cols m)
__device__ float g_sn[NSEL], g_sm[NSEL], g_bps[NSEL], g_bp[NSEL];

// ---------------- gather (+ accumulator reset) ----------------
__global__ void gather_kernel(const int* __restrict__ nodes_p_star,
                              const int* __restrict__ nodes_p,
                              const float* __restrict__ beta_p,
                              const float* __restrict__ beta_p_star,
                              const float* __restrict__ p,
                              const float* __restrict__ p_star) {
    if (blockIdx.x == 0 && threadIdx.x < 3) {
        if (threadIdx.x < 2) g_acc[threadIdx.x] = 0.0;
        else g_done = 0u;
    }
    int w    = (blockIdx.x * blockDim.x + threadIdx.x) >> 5;
    int lane = threadIdx.x & 31;
    if (w >= 2 * NSEL) return;
    bool is_s = (w < NSEL);
    int row   = is_s ? w : (w - NSEL);
    int node  = is_s ? nodes_p_star[row] : nodes_p[row];
    const float4* src = reinterpret_cast<const float4*>((is_s ? p_star : p) + (size_t)node * DIM);
    float4 v = src[lane];

    __nv_bfloat162 h0 = __floats2bfloat162_rn(v.x, v.y);
    __nv_bfloat162 h1 = __floats2bfloat162_rn(v.z, v.w);
    uint2 packed;
    packed.x = *reinterpret_cast<unsigned*>(&h0);
    packed.y = *reinterpret_cast<unsigned*>(&h1);
    __nv_bfloat16* dstb = (is_s ? g_psb : g_ppb) + (size_t)row * DIM;
    reinterpret_cast<uint2*>(dstb)[lane] = packed;

    float s = v.x * v.x + v.y * v.y + v.z * v.z + v.w * v.w;
    #pragma unroll
    for (int o = 16; o > 0; o >>= 1) s += __shfl_xor_sync(0xffffffffu, s, o);
    if (lane == 0) {
        if (is_s) { g_sn[row] = s; g_bps[row] = beta_p_star[node]; }
        else      { g_sm[row] = s; g_bp[row]  = beta_p[node]; }
    }
}

// ---------------- helpers ----------------
__device__ __forceinline__ uint32_t cvta_s(const void* ptr) {
    return (uint32_t)__cvta_generic_to_shared(ptr);
}
__device__ __forceinline__ void cp16(uint32_t s, const void* g) {
    asm volatile("cp.async.cg.shared.global [%0], [%1], 16;" :: "r"(s), "l"(g));
}
#define CP_COMMIT() asm volatile("cp.async.commit_group;")
#define CP_WAIT1()  asm volatile("cp.async.wait_group 1;")
#define CP_WAIT0()  asm volatile("cp.async.wait_group 0;")
#define BAR_SYNC(id, cnt)   asm volatile("bar.sync %0, %1;"   :: "r"(id), "r"(cnt) : "memory")
#define BAR_ARRIVE(id, cnt) asm volatile("bar.arrive %0, %1;" :: "r"(id), "r"(cnt) : "memory")
__device__ __forceinline__ void ldsm_x4(uint32_t* r, uint32_t addr) {
    asm volatile("ldmatrix.sync.aligned.m8n8.x4.shared.b16 {%0,%1,%2,%3}, [%4];"
                 : "=r"(r[0]), "=r"(r[1]), "=r"(r[2]), "=r"(r[3]) : "r"(addr));
}
__device__ __forceinline__ void mma_bf16(float* c, const uint32_t* a, const uint32_t* b) {
    asm volatile("mma.sync.aligned.m16n8k16.row.col.f32.bf16.bf16.f32 "
                 "{%0,%1,%2,%3}, {%4,%5,%6,%7}, {%8,%9}, {%0,%1,%2,%3};"
                 : "+f"(c[0]), "+f"(c[1]), "+f"(c[2]), "+f"(c[3])
                 : "r"(a[0]), "r"(a[1]), "r"(a[2]), "r"(a[3]), "r"(b[0]), "r"(b[1]));
}
__device__ __forceinline__ float fast_sqrt(float x) {
    float r; asm("sqrt.approx.f32 %0, %1;" : "=f"(r) : "f"(x)); return r;
}
__device__ __forceinline__ float fast_ex2(float x) {
    float r; asm("ex2.approx.f32 %0, %1;" : "=f"(r) : "f"(x)); return r;
}

// Upper-tri enumeration of 128(row)x64(col) tiles: tile (bi,bj) live iff bj >= 2*bi.
// offset(i) = i*(257 - i); row i owns bj = 2i .. 255.
__device__ __forceinline__ void tile_ij2(int t, int& bi, int& bj) {
    float disc = 257.f * 257.f - 4.f * (float)t;
    int i = (int)((257.f - sqrtf(disc)) * 0.5f);
    if (i < 0) i = 0;
    if (i > 127) i = 127;
    while (i > 0 && i * (257 - i) > t) i--;
    while (i < 127 && (i + 1) * (257 - (i + 1)) <= t) i++;
    bi = i;
    bj = 2 * i + (t - i * (257 - i));
}

// ---------------- fused persistent warp-specialized kernel ----------------
// Warps 0-3: producers (cp.async tile load + ldmatrix + HMMA -> fp32 acc -> smem).
// Warps 4-7: consumers (sqrt/exp epilogue from smem acc). Named barriers:
//  bar1 acc-full (prod fence+arrive / cons sync), bar2 acc-free (cons arrive / prod sync),
//  bar3/bar5 producer-internal stage barriers.
__global__ void __launch_bounds__(256, 2) fused_kernel(
        const int* __restrict__ edges,
        const float* __restrict__ beta_p,
        const float* __restrict__ beta_p_star,
        const float* __restrict__ p,
        const float* __restrict__ p_star,
        float* __restrict__ out) {
    extern __shared__ __align__(16) char dynraw[];
    __shared__ float2 csb[2][64];          // col {norm, beta*log2e}, double-buffered
    __shared__ float red[8], redl[8];

    const float LOG2E = 1.4426950408889634f;
    int bid = blockIdx.x, tid = threadIdx.x, wid = tid >> 5, lane = tid & 31;

    char* dynC = (char*)(((uintptr_t)dynraw + 127) & ~(uintptr_t)127);
    uint32_t smbase = cvta_s(dynC);
    char* accC = dynC + 2 * STAGEB;

    int nt = (NTRI2 - bid + NTC - 1) / NTC;   // tiles owned: t = bid + k*NTC  (>=55 always)

    float part = 0.f, lsum = 0.f;

    if (wid < 4) {
        // ================= PRODUCERS (128 threads; tid = 0..127) =================
        int ecur = bid * 4 + wid;
        auto link_batch4 = [&]() {
            #pragma unroll
            for (int k = 0; k < 4; k++) {
                int ei = ecur + k * NW_L;
                if (ei < NEDGE) {
                    int e0 = edges[ei];
                    int e1 = edges[NEDGE + ei];
                    float4 a = reinterpret_cast<const float4*>(p      + (size_t)e0 * DIM)[lane];
                    float4 b = reinterpret_cast<const float4*>(p_star + (size_t)e1 * DIM)[lane];
                    float dx = a.x - b.x + EPS_LDM;
                    float dy = a.y - b.y + EPS_LDM;
                    float dz = a.z - b.z + EPS_LDM;
                    float dw = a.w - b.w + EPS_LDM;
                    float s = dx * dx + dy * dy + dz * dz + dw * dw;
                    #pragma unroll
                    for (int o = 16; o > 0; o >>= 1) s += __shfl_xor_sync(0xffffffffu, s, o);
                    if (lane == 0) lsum += beta_p_star[e0] + beta_p[e1] - sqrtf(s);
                }
            }
            ecur += 4 * NW_L;
        };
        auto prefetch_stage = [&](int s) {
            int t = bid + (s >> 1) * NTC;
            int bi, bj;
            tile_ij2(t, bi, bj);
            int n0 = bi << 7, m0 = bj << 6, koff = (s & 1) * 64;
            uint32_t buf = smbase + (uint32_t)(s & 1) * STAGEB;
            #pragma unroll
            for (int k = 0; k < 8; k++) {            // A: 128 rows x 8 chunks
                int idx = tid + k * 128;
                int row = idx >> 3, c = idx & 7;
                cp16(buf + row * ROWB2 + c * 16,
                     g_psb + (size_t)(n0 + row) * DIM + koff + c * 8);
            }
            #pragma unroll
            for (int k = 0; k < 4; k++) {            // B: 64 rows x 8 chunks
                int idx = tid + k * 128;
                int row = idx >> 3, c = idx & 7;
                cp16(buf + A_BYTES + row * ROWB2 + c * 16,
                     g_ppb + (size_t)(m0 + row) * DIM + koff + c * 8);
            }
            CP_COMMIT();
        };

        float acc[2][8][4];
        int ns = 2 * nt;
        prefetch_stage(0);
        int s = 0;
        for (int ti = 0; ti < nt; ti++) {
            #pragma unroll 1
            for (int ph = 0; ph < 2; ph++, s++) {
                if (s + 1 < ns) prefetch_stage(s + 1);
                link_batch4();                     // LDG latency hides under cp.async
                if (s + 1 < ns) { CP_WAIT1(); } else { CP_WAIT0(); }
                BAR_SYNC(3, 128);                  // stage data visible to all producers
                if (ph == 0) {
                    #pragma unroll
                    for (int g = 0; g < 2; g++)
                        #pragma unroll
                        for (int j = 0; j < 8; j++)
                            #pragma unroll
                            for (int q = 0; q < 4; q++) acc[g][j][q] = 0.f;
                }
                uint32_t bufA = smbase + (uint32_t)(s & 1) * STAGEB;
                uint32_t bufB = bufA + A_BYTES;
                #pragma unroll
                for (int ks = 0; ks < 4; ks++) {
                    int kb = (ks * 16 + ((lane >> 4) << 3)) * 2;
                    uint32_t a[2][4];
                    #pragma unroll
                    for (int g = 0; g < 2; g++) {
                        int row = wid * 32 + g * 16 + (lane & 15);
                        ldsm_x4(a[g], bufA + row * ROWB2 + kb);
                    }
                    uint32_t b[8][2];
                    #pragma unroll
                    for (int h = 0; h < 4; h++) {
                        int row = h * 16 + (lane & 15);
                        uint32_t r[4];
                        ldsm_x4(r, bufB + row * ROWB2 + kb);
                        b[2 * h + 0][0] = r[0]; b[2 * h + 0][1] = r[2];
                        b[2 * h + 1][0] = r[1]; b[2 * h + 1][1] = r[3];
                    }
                    #pragma unroll
                    for (int g = 0; g < 2; g++)
                        #pragma unroll
                        for (int j = 0; j < 8; j++)
                            mma_bf16(acc[g][j], a[g], b[j]);
                }
                BAR_SYNC(5, 128);                  // stage buffer free for prefetch reuse
            }
            if (ti > 0) BAR_SYNC(2, 256);          // wait consumers freed acc buffer
            #pragma unroll
            for (int g = 0; g < 2; g++)
                #pragma unroll
                for (int j = 0; j < 8; j++) {
                    int row = wid * 32 + g * 16 + (lane >> 2);
                    int col = j * 8 + (lane & 3) * 2;
                    *reinterpret_cast<float2*>(accC + row * ACC_STRIDE + col * 4)
                        = make_float2(acc[g][j][0], acc[g][j][1]);
                    *reinterpret_cast<float2*>(accC + (row + 8) * ACC_STRIDE + col * 4)
                        = make_float2(acc[g][j][2], acc[g][j][3]);
                }
            __threadfence_block();                 // make acc STS visible before arrive
            BAR_ARRIVE(1, 256);                    // acc full
        }
        BAR_SYNC(2, 256);                          // balance final consumer free-arrival
        while (ecur < NEDGE) link_batch4();        // drain leftover edges
    } else {
        // ================= CONSUMERS (128 threads) =================
        int r = (wid - 4) * 32 + lane;             // output row 0..127
        for (int ti = 0; ti < nt; ti++) {
            int t = bid + ti * NTC;
            int bi, bj;
            tile_ij2(t, bi, bj);
            int n0 = bi << 7, m0 = bj << 6;
            int tb = ti & 1;
            if (wid == 4) {                        // stage col norms/betas (double-buffered)
                csb[tb][lane]      = make_float2(g_sm[m0 + lane],      g_bp[m0 + lane] * LOG2E);
                csb[tb][lane + 32] = make_float2(g_sm[m0 + lane + 32], g_bp[m0 + lane + 32] * LOG2E);
            }
            float rs = g_sn[n0 + r];
            float rb = g_bps[n0 + r] * LOG2E;
            BAR_SYNC(1, 256);                      // acc ready (bar.sync drains wid4's STS too)

            float s4[4] = {0.f, 0.f, 0.f, 0.f};
            const char* arow = accC + r * ACC_STRIDE;
            if (bj > 2 * bi + 1) {                 // fully above diagonal
                #pragma unroll
                for (int c0 = 0; c0 < 64; c0 += 4) {
                    float4 av = *reinterpret_cast<const float4*>(arow + c0 * 4);
                    #pragma unroll
                    for (int k = 0; k < 4; k++) {
                        float2 cc = csb[tb][c0 + k];
                        float a  = (&av.x)[k];
                        float sq = fmaf(-2.f, a, rs + cc.x);
                        float d  = fast_sqrt(sq);
                        s4[k] += fast_ex2(fmaf(d, -LOG2E, rb + cc.y));
                    }
                }
            } else {                               // diagonal-crossing tile: mask m > n
                #pragma unroll
                for (int c0 = 0; c0 < 64; c0 += 4) {
                    float4 av = *reinterpret_cast<const float4*>(arow + c0 * 4);
                    #pragma unroll
                    for (int k = 0; k < 4; k++) {
                        if (m0 + c0 + k > n0 + r) {
                            float2 cc = csb[tb][c0 + k];
                            float a  = (&av.x)[k];
                            float sq = fmaf(-2.f, a, rs + cc.x);
                            float d  = fast_sqrt(sq);
                            s4[k] += fast_ex2(fmaf(d, -LOG2E, rb + cc.y));
                        }
                    }
                }
            }
            part += (s4[0] + s4[1]) + (s4[2] + s4[3]);
            BAR_ARRIVE(2, 256);                    // acc buffer free (WAR; no fence needed)
        }
    }

    // --- reductions + finalize ---
    #pragma unroll
    for (int o = 16; o > 0; o >>= 1) {
        part += __shfl_xor_sync(0xffffffffu, part, o);
        lsum += __shfl_xor_sync(0xffffffffu, lsum, o);
    }
    if (lane == 0) { red[wid] = part; redl[wid] = lsum; }
    __syncthreads();
    if (tid == 0) {
        float bs = 0.f, bl = 0.f;
        #pragma unroll
        for (int i = 0; i < 8; i++) { bs += red[i]; bl += redl[i]; }
        atomicAdd(&g_acc[1], (double)bs);
        atomicAdd(&g_acc[0], (double)bl);
        __threadfence();
        unsigned v = atomicAdd(&g_done, 1u);
        if (v == NTC - 1) {
            __threadfence();
            double link = *(volatile double*)&g_acc[0];
            double nonl = *(volatile double*)&g_acc[1];
            out[0] = (float)(nonl - link);
        }
    }
}

extern "C" void kernel_launch(void* const* d_in, const int* in_sizes, int n_in,
                              void* d_out, int out_size) {
    const int*   edges        = (const int*)d_in[0];
    const int*   nodes_p_star = (const int*)d_in[1];
    const int*   nodes_p      = (const int*)d_in[2];
    const float* beta_p       = (const float*)d_in[3];
    const float* beta_p_star  = (const float*)d_in[4];
    const float* p            = (const float*)d_in[5];
    const float* p_star       = (const float*)d_in[6];
    float*       out          = (float*)d_out;

    cudaFuncSetAttribute(fused_kernel, cudaFuncAttributeMaxDynamicSharedMemorySize, DSMEM);

    gather_kernel<<<(2 * NSEL + 7) / 8, 256>>>(nodes_p_star, nodes_p,
                                               beta_p, beta_p_star, p, p_star);

    fused_kernel<<<NTC, 256, DSMEM>>>(edges, beta_p, beta_p_star, p, p_star, out);
}